// round 1
// baseline (speedup 1.0000x reference)
#include <cuda_runtime.h>

// ---------------------------------------------------------------------------
// PartialAttentionBlock: algebraic restructuring.
//   out[t] = 0.5 * ( softmaxN(G+Bn)·V + vn + softmaxC(G+Bc, seg==c_t)·V + vc )
// where G = q·k (one GEMM), B_c[s] = qtok_c · k_s (tiny precompute),
// row-constant logit terms cancel in softmax, counter == 2 always.
// ---------------------------------------------------------------------------

__device__ float g_tok[9 * 192];        // tokens: W_cls @ embed_table[c], c=0..8 (8 = null)
__device__ float g_B[64 * 9 * 1024];    // B[bh][c9][s] = qtok_c9 . k_{bh,s}

// ---- kernel A: class tokens --------------------------------------------------
__global__ void tok_kernel(const float* __restrict__ emb, const float* __restrict__ Wc)
{
    __shared__ float e[512];
    int c9 = blockIdx.x;
    for (int k = threadIdx.x; k < 512; k += blockDim.x) e[k] = emb[c9 * 512 + k];
    __syncthreads();
    int r = threadIdx.x;            // 0..191
    const float* w = Wc + r * 512;
    float acc = 0.f;
#pragma unroll 8
    for (int k = 0; k < 512; k++) acc = fmaf(w[k], e[k], acc);
    g_tok[c9 * 192 + r] = acc;
}

// ---- kernel B: key biases B[bh][c9][s] --------------------------------------
__global__ void bmat_kernel(const float* __restrict__ qkv)
{
    __shared__ float tq[9 * 64];
    int bh = blockIdx.x;
    for (int x = threadIdx.x; x < 576; x += blockDim.x)
        tq[x] = g_tok[(x >> 6) * 192 + (x & 63)];      // q-part of tokens
    __syncthreads();
    const float* kb = qkv + bh * 196608 + 65536;        // k plane of this bh
    for (int s = threadIdx.x; s < 1024; s += blockDim.x) {
        float acc[9];
#pragma unroll
        for (int c9 = 0; c9 < 9; c9++) acc[c9] = 0.f;
        for (int cc = 0; cc < 64; cc++) {
            float kv = kb[cc * 1024 + s];
#pragma unroll
            for (int c9 = 0; c9 < 9; c9++) acc[c9] = fmaf(tq[c9 * 64 + cc], kv, acc[c9]);
        }
#pragma unroll
        for (int c9 = 0; c9 < 9; c9++) g_B[bh * 9216 + c9 * 1024 + s] = acc[c9];
    }
}

// ---- main fused kernel -------------------------------------------------------
// grid (32 q-tiles, 64 bh), 256 threads, dynamic smem 207232 B (1 CTA/SM)
// smem layout (floats):
//   [0      , 32768) Ssm : scores / combined weights, swizzled (s*32 + (i ^ (s&31)))
//   [32768  , 34816) Qs  : Q tile [64][32] (c-major)
//   [34816  , 51200) KV  : K tile [64][256]  ->  V^T tile swizzled  ->  partials
//   [51200  , 51776) tokv: v-part of tokens [9][64]
//   [51776  , 51808) segq: per-query class (int)
__global__ void __launch_bounds__(256, 1)
attn_kernel(const float* __restrict__ qkv, const int* __restrict__ mask,
            float* __restrict__ out)
{
    extern __shared__ float sm[];
    float* Ssm  = sm;
    float* Qs   = sm + 32768;
    float* KV   = sm + 34816;
    float* tokv = sm + 51200;
    int*   segq = (int*)(sm + 51776);

    const int tid = threadIdx.x;
    const int bh  = blockIdx.y;
    const int t0  = blockIdx.x * 32;
    const int b   = bh >> 3;
    const float* qb = qkv + bh * 196608;

    // preload Q tile (c-major [64][32]), token v-parts, query segments
#pragma unroll
    for (int r = 0; r < 8; r++) {
        int f = tid + 256 * r;
        int c = f >> 5, i = f & 31;
        Qs[c * 32 + i] = qb[c * 1024 + t0 + i];
    }
    for (int x = tid; x < 576; x += 256)
        tokv[x] = g_tok[(x >> 6) * 192 + 128 + (x & 63)];
    if (tid < 32) segq[tid] = mask[b * 1024 + t0 + tid];

    // ================= phase 1: G = Q^T K =================
    const int qg = tid >> 5, sg = tid & 31;      // warp = fixed qg
    const float* kbase = qb + 65536;
    for (int tile = 0; tile < 4; tile++) {
        const int s0 = tile * 256;
        __syncthreads();
#pragma unroll
        for (int r = 0; r < 16; r++) {           // load K tile [64][256]
            int f = tid + 256 * r;
            int c = f >> 6, j4 = f & 63;
            float4 kv = *(const float4*)(kbase + c * 1024 + s0 + 4 * j4);
            *(float4*)(KV + c * 256 + 4 * j4) = kv;
        }
        __syncthreads();
        float acc[4][8];
#pragma unroll
        for (int a = 0; a < 4; a++)
#pragma unroll
            for (int bb = 0; bb < 8; bb++) acc[a][bb] = 0.f;
#pragma unroll 4
        for (int c = 0; c < 64; c++) {
            float4 q4  = *(const float4*)(Qs + c * 32 + 4 * qg);        // broadcast
            float4 ka  = *(const float4*)(KV + c * 256 + 4 * sg);       // contiguous
            float4 kb4 = *(const float4*)(KV + c * 256 + 128 + 4 * sg); // contiguous
            float qv[4] = {q4.x, q4.y, q4.z, q4.w};
            float kv[8] = {ka.x, ka.y, ka.z, ka.w, kb4.x, kb4.y, kb4.z, kb4.w};
#pragma unroll
            for (int a = 0; a < 4; a++)
#pragma unroll
                for (int bb = 0; bb < 8; bb++)
                    acc[a][bb] = fmaf(qv[a], kv[bb], acc[a][bb]);
        }
#pragma unroll
        for (int a = 0; a < 4; a++) {
            int i = 4 * qg + a;
#pragma unroll
            for (int bb = 0; bb < 8; bb++) {
                int s = s0 + ((bb < 4) ? (4 * sg + bb) : (128 + 4 * sg + bb - 4));
                Ssm[s * 32 + (i ^ (s & 31))] = acc[a][bb];
            }
        }
    }
    __syncthreads();

    // ================= phase 2: two softmaxes -> combined weights =================
    {
        const int warp = tid >> 5, lane = tid & 31;
        const float* Bn = g_B + bh * 9216 + 8192;   // null token biases
        const float* Bb = g_B + bh * 9216;
        const int* segs = mask + b * 1024;
        const float SC2 = 0.125f;                    // scale^2 = ch^-0.5
        for (int rr = 0; rr < 4; rr++) {
            int i = warp * 4 + rr;
            int ci = segq[i];
            const float* Bc = Bb + ci * 1024;
            float mN = -1e30f, mC = -1e30f;
            for (int k = 0; k < 32; k++) {
                int s = lane + 32 * k;
                float G = Ssm[s * 32 + (i ^ (s & 31))];
                mN = fmaxf(mN, SC2 * (G + Bn[s]));
                if (segs[s] == ci) mC = fmaxf(mC, SC2 * (G + Bc[s]));
            }
#pragma unroll
            for (int o = 16; o > 0; o >>= 1) {
                mN = fmaxf(mN, __shfl_xor_sync(0xffffffffu, mN, o));
                mC = fmaxf(mC, __shfl_xor_sync(0xffffffffu, mC, o));
            }
            float sN = 0.f, sC = 0.f;
            for (int k = 0; k < 32; k++) {
                int s = lane + 32 * k;
                float G = Ssm[s * 32 + (i ^ (s & 31))];
                sN += __expf(SC2 * (G + Bn[s]) - mN);
                if (segs[s] == ci) sC += __expf(SC2 * (G + Bc[s]) - mC);
            }
#pragma unroll
            for (int o = 16; o > 0; o >>= 1) {
                sN += __shfl_xor_sync(0xffffffffu, sN, o);
                sC += __shfl_xor_sync(0xffffffffu, sC, o);
            }
            float rN = 1.f / sN, rC = 1.f / sC;
            for (int k = 0; k < 32; k++) {
                int s = lane + 32 * k;
                int idx = s * 32 + (i ^ (s & 31));
                float G = Ssm[idx];
                float w = __expf(SC2 * (G + Bn[s]) - mN) * rN;
                if (segs[s] == ci) w += __expf(SC2 * (G + Bc[s]) - mC) * rC;
                Ssm[idx] = w;                        // combined weight
            }
        }
    }
    __syncthreads();

    // ================= phase 3: out = W . V (split-s x4) =================
    {
        const int grp = tid >> 6;             // s-quarter within tile
        const int qg3 = (tid >> 3) & 7;
        const int cg  = tid & 7;
        const float* vbase = qb + 131072;
        float acc[4][8];
#pragma unroll
        for (int m = 0; m < 4; m++)
#pragma unroll
            for (int n = 0; n < 8; n++) acc[m][n] = 0.f;

        for (int tile = 0; tile < 4; tile++) {
            const int s0 = tile * 256;
            __syncthreads();
#pragma unroll
            for (int r = 0; r < 16; r++) {    // load V tile transposed+swizzled
                int f = tid + 256 * r;
                int c = f >> 6, j4 = f & 63;
                float4 vv = *(const float4*)(vbase + c * 1024 + s0 + 4 * j4);
                int cs = c ^ (j4 & 31);
                KV[(4 * j4 + 0) * 64 + cs] = vv.x;
                KV[(4 * j4 + 1) * 64 + cs] = vv.y;
                KV[(4 * j4 + 2) * 64 + cs] = vv.z;
                KV[(4 * j4 + 3) * 64 + cs] = vv.w;
            }
            __syncthreads();
#pragma unroll 2
            for (int jj = 0; jj < 64; jj++) {
                int j = grp * 64 + jj;
                int s = s0 + j;
                int sk = s & 31;
                int vk = (j >> 2) & 31;
                float wv[4], vv[8];
#pragma unroll
                for (int m = 0; m < 4; m++) wv[m] = Ssm[s * 32 + ((4 * qg3 + m) ^ sk)];
#pragma unroll
                for (int n = 0; n < 8; n++) vv[n] = KV[j * 64 + ((8 * cg + n) ^ vk)];
#pragma unroll
                for (int m = 0; m < 4; m++)
#pragma unroll
                    for (int n = 0; n < 8; n++)
                        acc[m][n] = fmaf(wv[m], vv[n], acc[m][n]);
            }
        }
        __syncthreads();
        // partials into KV: [grp][c][i]
#pragma unroll
        for (int m = 0; m < 4; m++)
#pragma unroll
            for (int n = 0; n < 8; n++)
                KV[grp * 2048 + (8 * cg + n) * 32 + (4 * qg3 + m)] = acc[m][n];
    }
    __syncthreads();

    // ================= epilogue: reduce, add token v-parts, /2, store ==========
    {
        int i = tid & 31, cb = tid >> 5;
        int ci = segq[i];
#pragma unroll
        for (int rr = 0; rr < 8; rr++) {
            int c = cb * 8 + rr;
            float sum = KV[c * 32 + i] + KV[2048 + c * 32 + i]
                      + KV[4096 + c * 32 + i] + KV[6144 + c * 32 + i];
            float val = 0.5f * (sum + tokv[512 + c] + tokv[ci * 64 + c]);
            // output flat index: c*(bH*T) + bh*T + t
            out[c * 65536 + bh * 1024 + t0 + i] = val;
        }
    }
}

// ---------------------------------------------------------------------------
extern "C" void kernel_launch(void* const* d_in, const int* in_sizes, int n_in,
                              void* d_out, int out_size)
{
    const float* qkv  = (const float*)d_in[0];
    const int*   mask = (const int*)  d_in[1];
    const float* emb  = (const float*)d_in[2];
    const float* Wc   = (const float*)d_in[3];
    float* out = (float*)d_out;

    tok_kernel<<<9, 192>>>(emb, Wc);
    bmat_kernel<<<64, 256>>>(qkv);

    const int SMEM = 51808 * 4;   // 207232 B
    cudaFuncSetAttribute(attn_kernel, cudaFuncAttributeMaxDynamicSharedMemorySize, SMEM);
    attn_kernel<<<dim3(32, 64), 256, SMEM>>>(qkv, mask, out);
}